// round 9
// baseline (speedup 1.0000x reference)
#include <cuda_runtime.h>
#include <math.h>
#include <stdint.h>

#define T_TOK 2048   // B*S
#define H_DIM 2048
#define I_DIM 4096
#define E_NUM 8

// ---------------- scratch (device globals; no runtime allocation) ----------
__device__ __align__(256) float g_scale[E_NUM];
__device__ __align__(256) float g_act_exp[E_NUM * I_DIM];
__device__ __align__(256) float g_expert_sum[H_DIM];
__device__ __align__(256) float g_act[(size_t)T_TOK * I_DIM];   // tf32-rounded act
__device__ __align__(256) float g_hs_t[(size_t)T_TOK * H_DIM];  // tf32-rounded hs

// ============================ helpers ======================================
__device__ __forceinline__ uint32_t rna_bits_f(float x) {
    uint32_t r;
    asm("cvt.rna.tf32.f32 %0, %1;" : "=r"(r) : "f"(x));
    return r;
}
__device__ __forceinline__ uint32_t rna_bits(uint32_t bits) {
    return rna_bits_f(__uint_as_float(bits));
}

#define LDSM_X4(r0, r1, r2, r3, addr) \
    asm volatile("ldmatrix.sync.aligned.m8n8.x4.shared.b16 {%0,%1,%2,%3}, [%4];" \
                 : "=r"(r0), "=r"(r1), "=r"(r2), "=r"(r3) : "r"(addr))

#define MMA_TF32(d, a, b0, b1) \
    asm volatile("mma.sync.aligned.m16n8k8.row.col.f32.tf32.tf32.f32 " \
                 "{%0,%1,%2,%3}, {%4,%5,%6,%7}, {%8,%9}, {%0,%1,%2,%3};" \
                 : "+f"((d)[0]), "+f"((d)[1]), "+f"((d)[2]), "+f"((d)[3]) \
                 : "r"((a)[0]), "r"((a)[1]), "r"((a)[2]), "r"((a)[3]), \
                   "r"(b0), "r"(b1))

// ===================== tf32 rounding pass (hs only, 16 MB) =================
__global__ void tf32_round_kernel(const float4* __restrict__ in,
                                  uint4* __restrict__ out, int n4) {
    int i = blockIdx.x * 256 + threadIdx.x;
    if (i >= n4) return;
    float4 v = in[i];
    uint4 o;
    o.x = rna_bits_f(v.x); o.y = rna_bits_f(v.y);
    o.z = rna_bits_f(v.z); o.w = rna_bits_f(v.w);
    out[i] = o;
}

// ============================ shared tiling constants ======================
#define LDS_F 36                        // floats per smem row (32 + 4 pad)
#define TILE_F (128 * LDS_F)            // 4608 floats per 128x32 operand tile
#define TILE_B (TILE_F * 4)             // 18432 bytes

// =================== FUSED gate+up GEMM ====================================
// A = hs_t [T,H] (pre-rounded tf32), Bg = sgw, Bu = suw [I,H] raw fp32.
// Per CTA: 128x128 output tile of BOTH gate and up; epilogue writes
// act = rna(silu(gate)*up) to C. 8 warps (2x4), warp tile 64x32 each matrix.
#define FSTAGE_B (3 * TILE_B)           // A + Bg + Bu per stage = 55296
#define FUSED_SMEM (2 * FSTAGE_B)       // 110592

__device__ __forceinline__ void load_tile3(const float* __restrict__ A,
                                           const float* __restrict__ Bg,
                                           const float* __restrict__ Bu,
                                           int K, int bm, int bn,
                                           uint32_t sbase, int kt, int st,
                                           int tid) {
    const float* gA = A  + (size_t)bm * K + kt * 32;
    const float* gG = Bg + (size_t)bn * K + kt * 32;
    const float* gU = Bu + (size_t)bn * K + kt * 32;
    uint32_t s0 = sbase + st * FSTAGE_B;
#pragma unroll
    for (int j = 0; j < 12; j++) {
        int idx = tid + j * 256;            // 0..3071
        int t = idx >> 10;                  // 0=A 1=Bg 2=Bu
        int local = idx & 1023;
        int row = local >> 3, c4 = local & 7;
        const float* g = (t == 0 ? gA : (t == 1 ? gG : gU)) + (size_t)row * K + c4 * 4;
        uint32_t sa = s0 + t * TILE_B + row * (LDS_F * 4) + c4 * 16;
        asm volatile("cp.async.cg.shared.global [%0], [%1], 16;" :: "r"(sa), "l"(g));
    }
    asm volatile("cp.async.commit_group;" ::: "memory");
}

__global__ __launch_bounds__(256, 1)
void gemm_gateup_fused(const float* __restrict__ A, const float* __restrict__ Bg,
                       const float* __restrict__ Bu, float* __restrict__ C,
                       int K, int N) {
    extern __shared__ char smem[];
    uint32_t sbase = (uint32_t)__cvta_generic_to_shared(smem);
    const int tid = threadIdx.x;
    const int wid = tid >> 5, lane = tid & 31;
    const int warp_m = wid & 1, warp_n = wid >> 1;
    const int bm = blockIdx.y * 128, bn = blockIdx.x * 128;

    uint32_t a_off = ((warp_m * 64 + (lane & 7) + (lane & 8)) * LDS_F +
                      ((lane >> 4) & 1) * 4) * 4;
    uint32_t b_row = ((warp_n * 32 + (lane & 7) + ((lane >> 4) & 1) * 8) * LDS_F +
                      ((lane >> 3) & 1) * 4) * 4;

    float accg[4][4][4], accu[4][4][4];
#pragma unroll
    for (int i = 0; i < 4; i++)
#pragma unroll
        for (int j = 0; j < 4; j++)
#pragma unroll
            for (int q = 0; q < 4; q++) { accg[i][j][q] = 0.f; accu[i][j][q] = 0.f; }

    const int KT = K >> 5;
    load_tile3(A, Bg, Bu, K, bm, bn, sbase, 0, 0, tid);

    for (int kt = 0; kt < KT; kt++) {
        int st = kt & 1;
        if (kt + 1 < KT) {
            load_tile3(A, Bg, Bu, K, bm, bn, sbase, kt + 1, st ^ 1, tid);
            asm volatile("cp.async.wait_group 1;" ::: "memory");
        } else {
            asm volatile("cp.async.wait_group 0;" ::: "memory");
        }
        __syncthreads();

        uint32_t a_ptr  = sbase + st * FSTAGE_B + a_off;
        uint32_t bg_ptr = sbase + st * FSTAGE_B + TILE_B + b_row;
        uint32_t bu_ptr = sbase + st * FSTAGE_B + 2 * TILE_B + b_row;
#pragma unroll
        for (int ks = 0; ks < 4; ks++) {
            uint32_t a[4][4];
#pragma unroll
            for (int mt = 0; mt < 4; mt++)
                LDSM_X4(a[mt][0], a[mt][1], a[mt][2], a[mt][3],
                        a_ptr + (mt * 16 * LDS_F + ks * 8) * 4);   // pre-rounded
            uint32_t bg[2][4], bu[2][4];
#pragma unroll
            for (int ntp = 0; ntp < 2; ntp++) {
                LDSM_X4(bg[ntp][0], bg[ntp][1], bg[ntp][2], bg[ntp][3],
                        bg_ptr + (ntp * 16 * LDS_F + ks * 8) * 4);
                LDSM_X4(bu[ntp][0], bu[ntp][1], bu[ntp][2], bu[ntp][3],
                        bu_ptr + (ntp * 16 * LDS_F + ks * 8) * 4);
#pragma unroll
                for (int q = 0; q < 4; q++) {
                    bg[ntp][q] = rna_bits(bg[ntp][q]);
                    bu[ntp][q] = rna_bits(bu[ntp][q]);
                }
            }
#pragma unroll
            for (int mt = 0; mt < 4; mt++)
#pragma unroll
                for (int nt = 0; nt < 4; nt++) {
                    MMA_TF32(accg[mt][nt], a[mt],
                             bg[nt >> 1][(nt & 1) * 2], bg[nt >> 1][(nt & 1) * 2 + 1]);
                    MMA_TF32(accu[mt][nt], a[mt],
                             bu[nt >> 1][(nt & 1) * 2], bu[nt >> 1][(nt & 1) * 2 + 1]);
                }
        }
        __syncthreads();
    }

    // epilogue: act = rna( silu(gate) * up ), all in registers
    int lrow = lane >> 2, lcol = lane & 3;
    int col0 = bn + warp_n * 32;
#pragma unroll
    for (int mt = 0; mt < 4; mt++) {
#pragma unroll
        for (int h = 0; h < 2; h++) {
            int row = bm + warp_m * 64 + mt * 16 + lrow + h * 8;
            float* crow = C + (size_t)row * N + col0;
#pragma unroll
            for (int nt = 0; nt < 4; nt++) {
                int c = nt * 8 + lcol * 2;
                float gv0 = accg[mt][nt][h * 2 + 0], gv1 = accg[mt][nt][h * 2 + 1];
                float uv0 = accu[mt][nt][h * 2 + 0], uv1 = accu[mt][nt][h * 2 + 1];
                float v0 = gv0 / (1.f + expf(-gv0)) * uv0;
                float v1 = gv1 / (1.f + expf(-gv1)) * uv1;
                uint2 o = { rna_bits_f(v0), rna_bits_f(v1) };
                *reinterpret_cast<uint2*>(crow + c) = o;
            }
        }
    }
}

// =================== down GEMM: C = A @ B^T + bias =========================
// A = act (pre-rounded tf32), B = sdw raw fp32 (in-loop cvt on B only).
#define STAGE_B2 (2 * TILE_B)           // A + B per stage
#define DOWN_SMEM (2 * STAGE_B2)        // 73728

__device__ __forceinline__ void load_tile2(const float* __restrict__ A,
                                           const float* __restrict__ B,
                                           int K, int bm, int bn,
                                           uint32_t sbase, int kt, int st,
                                           int tid) {
    const float* gA = A + (size_t)bm * K + kt * 32;
    const float* gB = B + (size_t)bn * K + kt * 32;
    uint32_t s0 = sbase + st * STAGE_B2;
#pragma unroll
    for (int j = 0; j < 8; j++) {
        int idx = tid + j * 256;
        int isB = idx >> 10;
        int local = idx & 1023;
        int row = local >> 3, c4 = local & 7;
        const float* g = (isB ? gB : gA) + (size_t)row * K + c4 * 4;
        uint32_t sa = s0 + isB * TILE_B + row * (LDS_F * 4) + c4 * 16;
        asm volatile("cp.async.cg.shared.global [%0], [%1], 16;" :: "r"(sa), "l"(g));
    }
    asm volatile("cp.async.commit_group;" ::: "memory");
}

__global__ __launch_bounds__(256, 2)
void gemm_down(const float* __restrict__ A, const float* __restrict__ B,
               float* __restrict__ C, int K, int N,
               const float* __restrict__ bias) {
    extern __shared__ char smem[];
    uint32_t sbase = (uint32_t)__cvta_generic_to_shared(smem);
    const int tid = threadIdx.x;
    const int wid = tid >> 5, lane = tid & 31;
    const int warp_m = wid & 1, warp_n = wid >> 1;
    const int bm = blockIdx.y * 128, bn = blockIdx.x * 128;

    uint32_t a_off = ((warp_m * 64 + (lane & 7) + (lane & 8)) * LDS_F +
                      ((lane >> 4) & 1) * 4) * 4;
    uint32_t b_off = (uint32_t)TILE_B +
                     ((warp_n * 32 + (lane & 7) + ((lane >> 4) & 1) * 8) * LDS_F +
                      ((lane >> 3) & 1) * 4) * 4;

    float acc[4][4][4];
#pragma unroll
    for (int i = 0; i < 4; i++)
#pragma unroll
        for (int j = 0; j < 4; j++)
#pragma unroll
            for (int q = 0; q < 4; q++) acc[i][j][q] = 0.f;

    const int KT = K >> 5;
    load_tile2(A, B, K, bm, bn, sbase, 0, 0, tid);

    for (int kt = 0; kt < KT; kt++) {
        int st = kt & 1;
        if (kt + 1 < KT) {
            load_tile2(A, B, K, bm, bn, sbase, kt + 1, st ^ 1, tid);
            asm volatile("cp.async.wait_group 1;" ::: "memory");
        } else {
            asm volatile("cp.async.wait_group 0;" ::: "memory");
        }
        __syncthreads();

        uint32_t a_ptr = sbase + st * STAGE_B2 + a_off;
        uint32_t b_ptr = sbase + st * STAGE_B2 + b_off;
#pragma unroll
        for (int ks = 0; ks < 4; ks++) {
            uint32_t a[4][4];
#pragma unroll
            for (int mt = 0; mt < 4; mt++)
                LDSM_X4(a[mt][0], a[mt][1], a[mt][2], a[mt][3],
                        a_ptr + (mt * 16 * LDS_F + ks * 8) * 4);   // pre-rounded
            uint32_t b[2][4];
#pragma unroll
            for (int ntp = 0; ntp < 2; ntp++) {
                LDSM_X4(b[ntp][0], b[ntp][1], b[ntp][2], b[ntp][3],
                        b_ptr + (ntp * 16 * LDS_F + ks * 8) * 4);
#pragma unroll
                for (int q = 0; q < 4; q++) b[ntp][q] = rna_bits(b[ntp][q]);
            }
#pragma unroll
            for (int mt = 0; mt < 4; mt++)
#pragma unroll
                for (int nt = 0; nt < 4; nt++)
                    MMA_TF32(acc[mt][nt], a[mt],
                             b[nt >> 1][(nt & 1) * 2], b[nt >> 1][(nt & 1) * 2 + 1]);
        }
        __syncthreads();
    }

    int lrow = lane >> 2, lcol = lane & 3;
    int col0 = bn + warp_n * 32;
#pragma unroll
    for (int mt = 0; mt < 4; mt++) {
#pragma unroll
        for (int h = 0; h < 2; h++) {
            int row = bm + warp_m * 64 + mt * 16 + lrow + h * 8;
            float* crow = C + (size_t)row * N + col0;
#pragma unroll
            for (int nt = 0; nt < 4; nt++) {
                int c = nt * 8 + lcol * 2;
                float2 o = { acc[mt][nt][h * 2 + 0] + bias[col0 + c],
                             acc[mt][nt][h * 2 + 1] + bias[col0 + c + 1] };
                *reinterpret_cast<float2*>(crow + c) = o;
            }
        }
    }
}

// ---------------- router: logits, top-1 mask, sigmoid ----------------------
__global__ void router_kernel(const float* __restrict__ hs,
                              const float* __restrict__ rw,
                              float* __restrict__ scores /* [E, T] */) {
    int t = blockIdx.x;
    int tid = threadIdx.x;
    const float* x = hs + (size_t)t * H_DIM;

    float acc[E_NUM];
#pragma unroll
    for (int e = 0; e < E_NUM; e++) acc[e] = 0.f;
    for (int h = tid; h < H_DIM; h += 256) {
        float xv = x[h];
#pragma unroll
        for (int e = 0; e < E_NUM; e++) acc[e] += xv * rw[e * H_DIM + h];
    }
#pragma unroll
    for (int off = 16; off; off >>= 1) {
#pragma unroll
        for (int e = 0; e < E_NUM; e++)
            acc[e] += __shfl_down_sync(0xffffffffu, acc[e], off);
    }
    __shared__ float red[8][E_NUM];
    int warp = tid >> 5, lane = tid & 31;
    if (lane == 0) {
#pragma unroll
        for (int e = 0; e < E_NUM; e++) red[warp][e] = acc[e];
    }
    __syncthreads();
    if (tid == 0) {
        float logit[E_NUM];
#pragma unroll
        for (int e = 0; e < E_NUM; e++) {
            float s = 0.f;
#pragma unroll
            for (int w = 0; w < 8; w++) s += red[w][e];
            logit[e] = s;
        }
        int amax = 0; float best = logit[0];
#pragma unroll
        for (int e = 1; e < E_NUM; e++)
            if (logit[e] > best) { best = logit[e]; amax = e; }
        float sig = 1.f / (1.f + expf(-best));
#pragma unroll
        for (int e = 0; e < E_NUM; e++)
            scores[(size_t)e * T_TOK + t] = (e == amax) ? sig : 0.f;
        if (t < E_NUM) g_scale[t] = (amax == 0) ? sig : 0.f;
    }
}

// ---------------- expert gate/up GEMV (skips zero-score experts) -----------
__global__ void expert_gateup_kernel(const float* __restrict__ hs,
                                     const float* __restrict__ gw,
                                     const float* __restrict__ uw) {
    int e = blockIdx.y;
    float s = g_scale[e];
    if (s == 0.f) return;
    int warp = threadIdx.x >> 5, lane = threadIdx.x & 31;
    int i = blockIdx.x * 8 + warp;

    const float4* x4 = (const float4*)(hs + (size_t)e * H_DIM);
    const float4* g4 = (const float4*)(gw + ((size_t)e * I_DIM + i) * H_DIM);
    const float4* u4 = (const float4*)(uw + ((size_t)e * I_DIM + i) * H_DIM);

    float ga = 0.f, ua = 0.f;
    for (int k = lane; k < H_DIM / 4; k += 32) {
        float4 xv = x4[k], gv = g4[k], uv = u4[k];
        ga += xv.x * gv.x + xv.y * gv.y + xv.z * gv.z + xv.w * gv.w;
        ua += xv.x * uv.x + xv.y * uv.y + xv.z * uv.z + xv.w * uv.w;
    }
#pragma unroll
    for (int off = 16; off; off >>= 1) {
        ga += __shfl_down_sync(0xffffffffu, ga, off);
        ua += __shfl_down_sync(0xffffffffu, ua, off);
    }
    if (lane == 0) {
        ga *= s; ua *= s;
        float act = ga / (1.f + expf(-ga)) * ua;
        g_act_exp[e * I_DIM + i] = act;
    }
}

// ---------------- expert down GEMV + sum over experts ----------------------
__global__ void expert_down_kernel(const float* __restrict__ dw) {
    int h = blockIdx.x;
    int tid = threadIdx.x;
    float acc = 0.f;
    for (int e = 0; e < E_NUM; e++) {
        if (g_scale[e] == 0.f) continue;
        const float4* w4 = (const float4*)(dw + ((size_t)e * H_DIM + h) * I_DIM);
        const float4* a4 = (const float4*)(g_act_exp + e * I_DIM);
        for (int k = tid; k < I_DIM / 4; k += 256) {
            float4 wv = w4[k], av = a4[k];
            acc += wv.x * av.x + wv.y * av.y + wv.z * av.z + wv.w * av.w;
        }
    }
    __shared__ float red[256];
    red[tid] = acc;
    __syncthreads();
    for (int s = 128; s; s >>= 1) {
        if (tid < s) red[tid] += red[tid + s];
        __syncthreads();
    }
    if (tid == 0) g_expert_sum[h] = red[0];
}

// ---------------- launch --------------------------------------------------
extern "C" void kernel_launch(void* const* d_in, const int* in_sizes, int n_in,
                              void* d_out, int out_size) {
    const float* hs  = (const float*)d_in[0];
    const float* rw  = (const float*)d_in[1];
    const float* sgw = (const float*)d_in[2];
    const float* suw = (const float*)d_in[3];
    const float* sdw = (const float*)d_in[4];
    const float* egw = (const float*)d_in[5];
    const float* euw = (const float*)d_in[6];
    const float* edw = (const float*)d_in[7];

    float* out    = (float*)d_out;
    float* scores = out + (size_t)T_TOK * H_DIM;

    float *p_act, *p_hs, *p_esum;
    cudaGetSymbolAddress((void**)&p_act,  g_act);
    cudaGetSymbolAddress((void**)&p_hs,   g_hs_t);
    cudaGetSymbolAddress((void**)&p_esum, g_expert_sum);

    cudaFuncSetAttribute(gemm_gateup_fused,
                         cudaFuncAttributeMaxDynamicSharedMemorySize, FUSED_SMEM);
    cudaFuncSetAttribute(gemm_down,
                         cudaFuncAttributeMaxDynamicSharedMemorySize, DOWN_SMEM);

    // 0. pre-round hs to tf32 (A side of fused GEMM) — 16 MB, ~11 us
    int n4 = T_TOK * H_DIM / 4;
    tf32_round_kernel<<<n4 / 256, 256>>>((const float4*)hs, (uint4*)p_hs, n4);

    // 1. router (+ g_scale, router_scores output)
    router_kernel<<<T_TOK, 256>>>(hs, rw, scores);

    // 2-3. expert path (fp32 GEMV, data-dependent skip)
    expert_gateup_kernel<<<dim3(I_DIM / 8, E_NUM), 256>>>(hs, egw, euw);
    expert_down_kernel<<<H_DIM, 256>>>(edw);

    // 4. act = rna( silu(hs@sgw^T) * (hs@suw^T) )   [T, I]  (fully fused)
    gemm_gateup_fused<<<dim3(I_DIM / 128, T_TOK / 128), 256, FUSED_SMEM>>>(
        p_hs, sgw, suw, p_act, H_DIM, I_DIM);

    // 5. out = act @ sdw^T + expert_sum             [T, H]
    gemm_down<<<dim3(H_DIM / 128, T_TOK / 128), 256, DOWN_SMEM>>>(
        p_act, sdw, out, I_DIM, H_DIM, p_esum);
}

// round 10
// speedup vs baseline: 1.0022x; 1.0022x over previous
#include <cuda_runtime.h>
#include <math.h>
#include <stdint.h>

#define T_TOK 2048   // B*S
#define H_DIM 2048
#define I_DIM 4096
#define E_NUM 8

// ---------------- scratch (device globals; no runtime allocation) ----------
__device__ __align__(256) float g_scale[E_NUM];
__device__ __align__(256) float g_act_exp[E_NUM * I_DIM];
__device__ __align__(256) float g_expert_sum[H_DIM];
__device__ __align__(256) float g_act[(size_t)T_TOK * I_DIM];   // tf32-rounded act
__device__ __align__(256) float g_hs_t[(size_t)T_TOK * H_DIM];  // tf32-rounded hs

// ============================ helpers ======================================
__device__ __forceinline__ uint32_t rna_bits_f(float x) {
    uint32_t r;
    asm("cvt.rna.tf32.f32 %0, %1;" : "=r"(r) : "f"(x));
    return r;
}
__device__ __forceinline__ uint32_t rna_bits(uint32_t bits) {
    return rna_bits_f(__uint_as_float(bits));
}

#define LDSM_X4(r0, r1, r2, r3, addr) \
    asm volatile("ldmatrix.sync.aligned.m8n8.x4.shared.b16 {%0,%1,%2,%3}, [%4];" \
                 : "=r"(r0), "=r"(r1), "=r"(r2), "=r"(r3) : "r"(addr))

#define MMA_TF32(d, a, b0, b1) \
    asm volatile("mma.sync.aligned.m16n8k8.row.col.f32.tf32.tf32.f32 " \
                 "{%0,%1,%2,%3}, {%4,%5,%6,%7}, {%8,%9}, {%0,%1,%2,%3};" \
                 : "+f"((d)[0]), "+f"((d)[1]), "+f"((d)[2]), "+f"((d)[3]) \
                 : "r"((a)[0]), "r"((a)[1]), "r"((a)[2]), "r"((a)[3]), \
                   "r"(b0), "r"(b1))

// ===================== tf32 rounding pass (hs only, 16 MB) =================
__global__ void tf32_round_kernel(const float4* __restrict__ in,
                                  uint4* __restrict__ out, int n4) {
    int i = blockIdx.x * 256 + threadIdx.x;
    if (i >= n4) return;
    float4 v = in[i];
    uint4 o;
    o.x = rna_bits_f(v.x); o.y = rna_bits_f(v.y);
    o.z = rna_bits_f(v.z); o.w = rna_bits_f(v.w);
    out[i] = o;
}

// ============================ shared tiling constants ======================
#define LDS_F 36                        // floats per smem row (32 + 4 pad)
#define TILE_F (128 * LDS_F)            // 4608 floats per 128x32 operand tile
#define TILE_B (TILE_F * 4)             // 18432 bytes

// =================== FUSED gate+up GEMM ====================================
// A = hs_t [T,H] (pre-rounded tf32), Bg = sgw, Bu = suw [I,H] raw fp32.
// Per CTA: 128x128 output tile of BOTH gate and up; epilogue writes
// act = rna(silu(gate)*up) to C. 8 warps (2x4), warp tile 64x32 each matrix.
#define FSTAGE_B (3 * TILE_B)           // A + Bg + Bu per stage = 55296
#define FUSED_SMEM (2 * FSTAGE_B)       // 110592

__device__ __forceinline__ void load_tile3(const float* __restrict__ A,
                                           const float* __restrict__ Bg,
                                           const float* __restrict__ Bu,
                                           int K, int bm, int bn,
                                           uint32_t sbase, int kt, int st,
                                           int tid) {
    const float* gA = A  + (size_t)bm * K + kt * 32;
    const float* gG = Bg + (size_t)bn * K + kt * 32;
    const float* gU = Bu + (size_t)bn * K + kt * 32;
    uint32_t s0 = sbase + st * FSTAGE_B;
#pragma unroll
    for (int j = 0; j < 12; j++) {
        int idx = tid + j * 256;            // 0..3071
        int t = idx >> 10;                  // 0=A 1=Bg 2=Bu
        int local = idx & 1023;
        int row = local >> 3, c4 = local & 7;
        const float* g = (t == 0 ? gA : (t == 1 ? gG : gU)) + (size_t)row * K + c4 * 4;
        uint32_t sa = s0 + t * TILE_B + row * (LDS_F * 4) + c4 * 16;
        asm volatile("cp.async.cg.shared.global [%0], [%1], 16;" :: "r"(sa), "l"(g));
    }
    asm volatile("cp.async.commit_group;" ::: "memory");
}

__global__ __launch_bounds__(256, 1)
void gemm_gateup_fused(const float* __restrict__ A, const float* __restrict__ Bg,
                       const float* __restrict__ Bu, float* __restrict__ C,
                       int K, int N) {
    extern __shared__ char smem[];
    uint32_t sbase = (uint32_t)__cvta_generic_to_shared(smem);
    const int tid = threadIdx.x;
    const int wid = tid >> 5, lane = tid & 31;
    const int warp_m = wid & 1, warp_n = wid >> 1;
    const int bm = blockIdx.y * 128, bn = blockIdx.x * 128;

    uint32_t a_off = ((warp_m * 64 + (lane & 7) + (lane & 8)) * LDS_F +
                      ((lane >> 4) & 1) * 4) * 4;
    uint32_t b_row = ((warp_n * 32 + (lane & 7) + ((lane >> 4) & 1) * 8) * LDS_F +
                      ((lane >> 3) & 1) * 4) * 4;

    float accg[4][4][4], accu[4][4][4];
#pragma unroll
    for (int i = 0; i < 4; i++)
#pragma unroll
        for (int j = 0; j < 4; j++)
#pragma unroll
            for (int q = 0; q < 4; q++) { accg[i][j][q] = 0.f; accu[i][j][q] = 0.f; }

    const int KT = K >> 5;
    load_tile3(A, Bg, Bu, K, bm, bn, sbase, 0, 0, tid);

    for (int kt = 0; kt < KT; kt++) {
        int st = kt & 1;
        if (kt + 1 < KT) {
            load_tile3(A, Bg, Bu, K, bm, bn, sbase, kt + 1, st ^ 1, tid);
            asm volatile("cp.async.wait_group 1;" ::: "memory");
        } else {
            asm volatile("cp.async.wait_group 0;" ::: "memory");
        }
        __syncthreads();

        uint32_t a_ptr  = sbase + st * FSTAGE_B + a_off;
        uint32_t bg_ptr = sbase + st * FSTAGE_B + TILE_B + b_row;
        uint32_t bu_ptr = sbase + st * FSTAGE_B + 2 * TILE_B + b_row;
#pragma unroll
        for (int ks = 0; ks < 4; ks++) {
            uint32_t a[4][4];
#pragma unroll
            for (int mt = 0; mt < 4; mt++)
                LDSM_X4(a[mt][0], a[mt][1], a[mt][2], a[mt][3],
                        a_ptr + (mt * 16 * LDS_F + ks * 8) * 4);   // pre-rounded
            uint32_t bg[2][4], bu[2][4];
#pragma unroll
            for (int ntp = 0; ntp < 2; ntp++) {
                LDSM_X4(bg[ntp][0], bg[ntp][1], bg[ntp][2], bg[ntp][3],
                        bg_ptr + (ntp * 16 * LDS_F + ks * 8) * 4);
                LDSM_X4(bu[ntp][0], bu[ntp][1], bu[ntp][2], bu[ntp][3],
                        bu_ptr + (ntp * 16 * LDS_F + ks * 8) * 4);
#pragma unroll
                for (int q = 0; q < 4; q++) {
                    bg[ntp][q] = rna_bits(bg[ntp][q]);
                    bu[ntp][q] = rna_bits(bu[ntp][q]);
                }
            }
#pragma unroll
            for (int mt = 0; mt < 4; mt++)
#pragma unroll
                for (int nt = 0; nt < 4; nt++) {
                    MMA_TF32(accg[mt][nt], a[mt],
                             bg[nt >> 1][(nt & 1) * 2], bg[nt >> 1][(nt & 1) * 2 + 1]);
                    MMA_TF32(accu[mt][nt], a[mt],
                             bu[nt >> 1][(nt & 1) * 2], bu[nt >> 1][(nt & 1) * 2 + 1]);
                }
        }
        __syncthreads();
    }

    // epilogue: act = rna( silu(gate) * up ), all in registers
    int lrow = lane >> 2, lcol = lane & 3;
    int col0 = bn + warp_n * 32;
#pragma unroll
    for (int mt = 0; mt < 4; mt++) {
#pragma unroll
        for (int h = 0; h < 2; h++) {
            int row = bm + warp_m * 64 + mt * 16 + lrow + h * 8;
            float* crow = C + (size_t)row * N + col0;
#pragma unroll
            for (int nt = 0; nt < 4; nt++) {
                int c = nt * 8 + lcol * 2;
                float gv0 = accg[mt][nt][h * 2 + 0], gv1 = accg[mt][nt][h * 2 + 1];
                float uv0 = accu[mt][nt][h * 2 + 0], uv1 = accu[mt][nt][h * 2 + 1];
                float v0 = gv0 / (1.f + expf(-gv0)) * uv0;
                float v1 = gv1 / (1.f + expf(-gv1)) * uv1;
                uint2 o = { rna_bits_f(v0), rna_bits_f(v1) };
                *reinterpret_cast<uint2*>(crow + c) = o;
            }
        }
    }
}

// =================== down GEMM: C = A @ B^T + bias =========================
// A = act (pre-rounded tf32), B = sdw raw fp32 (in-loop cvt on B only).
#define STAGE_B2 (2 * TILE_B)           // A + B per stage
#define DOWN_SMEM (2 * STAGE_B2)        // 73728

__device__ __forceinline__ void load_tile2(const float* __restrict__ A,
                                           const float* __restrict__ B,
                                           int K, int bm, int bn,
                                           uint32_t sbase, int kt, int st,
                                           int tid) {
    const float* gA = A + (size_t)bm * K + kt * 32;
    const float* gB = B + (size_t)bn * K + kt * 32;
    uint32_t s0 = sbase + st * STAGE_B2;
#pragma unroll
    for (int j = 0; j < 8; j++) {
        int idx = tid + j * 256;
        int isB = idx >> 10;
        int local = idx & 1023;
        int row = local >> 3, c4 = local & 7;
        const float* g = (isB ? gB : gA) + (size_t)row * K + c4 * 4;
        uint32_t sa = s0 + isB * TILE_B + row * (LDS_F * 4) + c4 * 16;
        asm volatile("cp.async.cg.shared.global [%0], [%1], 16;" :: "r"(sa), "l"(g));
    }
    asm volatile("cp.async.commit_group;" ::: "memory");
}

__global__ __launch_bounds__(256, 2)
void gemm_down(const float* __restrict__ A, const float* __restrict__ B,
               float* __restrict__ C, int K, int N,
               const float* __restrict__ bias) {
    extern __shared__ char smem[];
    uint32_t sbase = (uint32_t)__cvta_generic_to_shared(smem);
    const int tid = threadIdx.x;
    const int wid = tid >> 5, lane = tid & 31;
    const int warp_m = wid & 1, warp_n = wid >> 1;
    const int bm = blockIdx.y * 128, bn = blockIdx.x * 128;

    uint32_t a_off = ((warp_m * 64 + (lane & 7) + (lane & 8)) * LDS_F +
                      ((lane >> 4) & 1) * 4) * 4;
    uint32_t b_off = (uint32_t)TILE_B +
                     ((warp_n * 32 + (lane & 7) + ((lane >> 4) & 1) * 8) * LDS_F +
                      ((lane >> 3) & 1) * 4) * 4;

    float acc[4][4][4];
#pragma unroll
    for (int i = 0; i < 4; i++)
#pragma unroll
        for (int j = 0; j < 4; j++)
#pragma unroll
            for (int q = 0; q < 4; q++) acc[i][j][q] = 0.f;

    const int KT = K >> 5;
    load_tile2(A, B, K, bm, bn, sbase, 0, 0, tid);

    for (int kt = 0; kt < KT; kt++) {
        int st = kt & 1;
        if (kt + 1 < KT) {
            load_tile2(A, B, K, bm, bn, sbase, kt + 1, st ^ 1, tid);
            asm volatile("cp.async.wait_group 1;" ::: "memory");
        } else {
            asm volatile("cp.async.wait_group 0;" ::: "memory");
        }
        __syncthreads();

        uint32_t a_ptr = sbase + st * STAGE_B2 + a_off;
        uint32_t b_ptr = sbase + st * STAGE_B2 + b_off;
#pragma unroll
        for (int ks = 0; ks < 4; ks++) {
            uint32_t a[4][4];
#pragma unroll
            for (int mt = 0; mt < 4; mt++)
                LDSM_X4(a[mt][0], a[mt][1], a[mt][2], a[mt][3],
                        a_ptr + (mt * 16 * LDS_F + ks * 8) * 4);   // pre-rounded
            uint32_t b[2][4];
#pragma unroll
            for (int ntp = 0; ntp < 2; ntp++) {
                LDSM_X4(b[ntp][0], b[ntp][1], b[ntp][2], b[ntp][3],
                        b_ptr + (ntp * 16 * LDS_F + ks * 8) * 4);
#pragma unroll
                for (int q = 0; q < 4; q++) b[ntp][q] = rna_bits(b[ntp][q]);
            }
#pragma unroll
            for (int mt = 0; mt < 4; mt++)
#pragma unroll
                for (int nt = 0; nt < 4; nt++)
                    MMA_TF32(acc[mt][nt], a[mt],
                             b[nt >> 1][(nt & 1) * 2], b[nt >> 1][(nt & 1) * 2 + 1]);
        }
        __syncthreads();
    }

    int lrow = lane >> 2, lcol = lane & 3;
    int col0 = bn + warp_n * 32;
#pragma unroll
    for (int mt = 0; mt < 4; mt++) {
#pragma unroll
        for (int h = 0; h < 2; h++) {
            int row = bm + warp_m * 64 + mt * 16 + lrow + h * 8;
            float* crow = C + (size_t)row * N + col0;
#pragma unroll
            for (int nt = 0; nt < 4; nt++) {
                int c = nt * 8 + lcol * 2;
                float2 o = { acc[mt][nt][h * 2 + 0] + bias[col0 + c],
                             acc[mt][nt][h * 2 + 1] + bias[col0 + c + 1] };
                *reinterpret_cast<float2*>(crow + c) = o;
            }
        }
    }
}

// ---------------- router: logits, top-1 mask, sigmoid ----------------------
__global__ void router_kernel(const float* __restrict__ hs,
                              const float* __restrict__ rw,
                              float* __restrict__ scores /* [E, T] */) {
    int t = blockIdx.x;
    int tid = threadIdx.x;
    const float* x = hs + (size_t)t * H_DIM;

    float acc[E_NUM];
#pragma unroll
    for (int e = 0; e < E_NUM; e++) acc[e] = 0.f;
    for (int h = tid; h < H_DIM; h += 256) {
        float xv = x[h];
#pragma unroll
        for (int e = 0; e < E_NUM; e++) acc[e] += xv * rw[e * H_DIM + h];
    }
#pragma unroll
    for (int off = 16; off; off >>= 1) {
#pragma unroll
        for (int e = 0; e < E_NUM; e++)
            acc[e] += __shfl_down_sync(0xffffffffu, acc[e], off);
    }
    __shared__ float red[8][E_NUM];
    int warp = tid >> 5, lane = tid & 31;
    if (lane == 0) {
#pragma unroll
        for (int e = 0; e < E_NUM; e++) red[warp][e] = acc[e];
    }
    __syncthreads();
    if (tid == 0) {
        float logit[E_NUM];
#pragma unroll
        for (int e = 0; e < E_NUM; e++) {
            float s = 0.f;
#pragma unroll
            for (int w = 0; w < 8; w++) s += red[w][e];
            logit[e] = s;
        }
        int amax = 0; float best = logit[0];
#pragma unroll
        for (int e = 1; e < E_NUM; e++)
            if (logit[e] > best) { best = logit[e]; amax = e; }
        float sig = 1.f / (1.f + expf(-best));
#pragma unroll
        for (int e = 0; e < E_NUM; e++)
            scores[(size_t)e * T_TOK + t] = (e == amax) ? sig : 0.f;
        if (t < E_NUM) g_scale[t] = (amax == 0) ? sig : 0.f;
    }
}

// ---------------- expert gate/up GEMV (skips zero-score experts) -----------
__global__ void expert_gateup_kernel(const float* __restrict__ hs,
                                     const float* __restrict__ gw,
                                     const float* __restrict__ uw) {
    int e = blockIdx.y;
    float s = g_scale[e];
    if (s == 0.f) return;
    int warp = threadIdx.x >> 5, lane = threadIdx.x & 31;
    int i = blockIdx.x * 8 + warp;

    const float4* x4 = (const float4*)(hs + (size_t)e * H_DIM);
    const float4* g4 = (const float4*)(gw + ((size_t)e * I_DIM + i) * H_DIM);
    const float4* u4 = (const float4*)(uw + ((size_t)e * I_DIM + i) * H_DIM);

    float ga = 0.f, ua = 0.f;
    for (int k = lane; k < H_DIM / 4; k += 32) {
        float4 xv = x4[k], gv = g4[k], uv = u4[k];
        ga += xv.x * gv.x + xv.y * gv.y + xv.z * gv.z + xv.w * gv.w;
        ua += xv.x * uv.x + xv.y * uv.y + xv.z * uv.z + xv.w * uv.w;
    }
#pragma unroll
    for (int off = 16; off; off >>= 1) {
        ga += __shfl_down_sync(0xffffffffu, ga, off);
        ua += __shfl_down_sync(0xffffffffu, ua, off);
    }
    if (lane == 0) {
        ga *= s; ua *= s;
        float act = ga / (1.f + expf(-ga)) * ua;
        g_act_exp[e * I_DIM + i] = act;
    }
}

// ---------------- expert down GEMV + sum over experts ----------------------
__global__ void expert_down_kernel(const float* __restrict__ dw) {
    int h = blockIdx.x;
    int tid = threadIdx.x;
    float acc = 0.f;
    for (int e = 0; e < E_NUM; e++) {
        if (g_scale[e] == 0.f) continue;
        const float4* w4 = (const float4*)(dw + ((size_t)e * H_DIM + h) * I_DIM);
        const float4* a4 = (const float4*)(g_act_exp + e * I_DIM);
        for (int k = tid; k < I_DIM / 4; k += 256) {
            float4 wv = w4[k], av = a4[k];
            acc += wv.x * av.x + wv.y * av.y + wv.z * av.z + wv.w * av.w;
        }
    }
    __shared__ float red[256];
    red[tid] = acc;
    __syncthreads();
    for (int s = 128; s; s >>= 1) {
        if (tid < s) red[tid] += red[tid + s];
        __syncthreads();
    }
    if (tid == 0) g_expert_sum[h] = red[0];
}

// ---------------- launch --------------------------------------------------
extern "C" void kernel_launch(void* const* d_in, const int* in_sizes, int n_in,
                              void* d_out, int out_size) {
    const float* hs  = (const float*)d_in[0];
    const float* rw  = (const float*)d_in[1];
    const float* sgw = (const float*)d_in[2];
    const float* suw = (const float*)d_in[3];
    const float* sdw = (const float*)d_in[4];
    const float* egw = (const float*)d_in[5];
    const float* euw = (const float*)d_in[6];
    const float* edw = (const float*)d_in[7];

    float* out    = (float*)d_out;
    float* scores = out + (size_t)T_TOK * H_DIM;

    float *p_act, *p_hs, *p_esum;
    cudaGetSymbolAddress((void**)&p_act,  g_act);
    cudaGetSymbolAddress((void**)&p_hs,   g_hs_t);
    cudaGetSymbolAddress((void**)&p_esum, g_expert_sum);

    cudaFuncSetAttribute(gemm_gateup_fused,
                         cudaFuncAttributeMaxDynamicSharedMemorySize, FUSED_SMEM);
    cudaFuncSetAttribute(gemm_down,
                         cudaFuncAttributeMaxDynamicSharedMemorySize, DOWN_SMEM);

    // 0. pre-round hs to tf32 (A side of fused GEMM) — 16 MB, ~11 us
    int n4 = T_TOK * H_DIM / 4;
    tf32_round_kernel<<<n4 / 256, 256>>>((const float4*)hs, (uint4*)p_hs, n4);

    // 1. router (+ g_scale, router_scores output)
    router_kernel<<<T_TOK, 256>>>(hs, rw, scores);

    // 2-3. expert path (fp32 GEMV, data-dependent skip)
    expert_gateup_kernel<<<dim3(I_DIM / 8, E_NUM), 256>>>(hs, egw, euw);
    expert_down_kernel<<<H_DIM, 256>>>(edw);

    // 4. act = rna( silu(hs@sgw^T) * (hs@suw^T) )   [T, I]  (fully fused)
    gemm_gateup_fused<<<dim3(I_DIM / 128, T_TOK / 128), 256, FUSED_SMEM>>>(
        p_hs, sgw, suw, p_act, H_DIM, I_DIM);

    // 5. out = act @ sdw^T + expert_sum             [T, H]
    gemm_down<<<dim3(H_DIM / 128, T_TOK / 128), 256, DOWN_SMEM>>>(
        p_act, sdw, out, I_DIM, H_DIM, p_esum);
}